// round 6
// baseline (speedup 1.0000x reference)
#include <cuda_runtime.h>

#define BATCH   1024
#define WDIM    256
#define HDIM    256
#define DEPTH   8
#define HMAX    256     // absolute worst-case hull size
#define HP      16      // padded fast-path hull size (Gaussian data: ~6-10 lines)

#define F_INF   __int_as_float(0x7F800000)
#define F_NINF  __int_as_float(0xFF800000)

// Static device scratch (allocation-free rule).
// Padded hulls: per (branch,d,w) exactly HP=16 lines (float2) = 128 bytes.
__device__ float2 g_hull [2][DEPTH][WDIM][HMAX];  // full hulls (rare fallback)
__device__ float4 g_hullp[2][DEPTH][WDIM][HP/2];  // 8 float4 = 128B per w
__device__ int    g_cnt  [2][DEPTH][WDIM];

// Monotone float -> uint key (uint order == float order, incl. +-inf).
__device__ __forceinline__ unsigned fkey(float f) {
    unsigned u = __float_as_uint(f);
    return (u & 0x80000000u) ? ~u : (u | 0x80000000u);
}

#define CP_ASYNC16(dst, src) \
    asm volatile("cp.async.cg.shared.global [%0], [%1], 16;" :: "r"(dst), "l"(src))
#define CP_COMMIT() asm volatile("cp.async.commit_group;")
#define CP_WAIT(n)  asm volatile("cp.async.wait_group %0;" :: "n"(n))

// ───────────────────────── hull kernel ─────────────────────────
// One warp per envelope (branch, d, w): gift-wrap the upper envelope of the
// 256 lines y = m*q + b. fp32 only; warp argmin via REDUX on ordered keys.
__global__ void __launch_bounds__(256) hull_kernel(
    const float* __restrict__ M1, const float* __restrict__ B1,
    const float* __restrict__ M2, const float* __restrict__ B2) {
    const int gw     = (blockIdx.x * blockDim.x + threadIdx.x) >> 5;  // 0..4095
    const int lane   = threadIdx.x & 31;
    const int branch = gw >> 11;
    const int d      = (gw >> 8) & 7;
    const int w      = gw & 255;

    const float* Mp = (branch ? M2 : M1) + (size_t)((d << 8) + w) * HDIM;
    const float* Bp = (branch ? B2 : B1) + (size_t)((d << 8) + w) * HDIM;

    float m[8], b[8];
#pragma unroll
    for (int k = 0; k < 8; k++) {
        m[k] = Mp[lane + (k << 5)];
        b[k] = Bp[lane + (k << 5)];
    }

    // Start line: min slope (dominated equal-slope start self-corrects step 1).
    float mc = m[0], bc = b[0];
#pragma unroll
    for (int k = 1; k < 8; k++)
        if (m[k] < mc || (m[k] == mc && b[k] > bc)) { mc = m[k]; bc = b[k]; }
    {
        unsigned mk = __reduce_min_sync(0xFFFFFFFFu, fkey(mc));
        unsigned bal = __ballot_sync(0xFFFFFFFFu, fkey(mc) == mk);
        int src = __ffs(bal) - 1;
        mc = __shfl_sync(0xFFFFFFFFu, mc, src);
        bc = __shfl_sync(0xFFFFFFFFu, bc, src);
    }

    float2* hf = &g_hull[branch][d][w][0];
    float2* hp = (float2*)&g_hullp[branch][d][w][0];   // 16 float2 slots = 128B
    const unsigned KEY_INF = fkey(F_INF);

    int cnt = 0;
    for (int step = 0; step < HMAX; ++step) {
        if (lane == 0) {
            hf[cnt] = make_float2(mc, bc);
            if (cnt < HP) hp[cnt] = make_float2(mc, bc);
        }
        cnt++;

        // Per-lane best candidate: smallest crossing x among overtaking lines.
        float bx = F_INF, bm = 0.f, bb = 0.f;
#pragma unroll
        for (int k = 0; k < 8; k++) {
            float dj = m[k] - mc;
            float nj = bc - b[k];
            bool valid = (dj > 0.f) || (dj == 0.f && nj < 0.f);
            float x = valid ? __fdividef(nj, dj) : F_INF;
            if (x < bx) { bx = x; bm = m[k]; bb = b[k]; }
        }
        unsigned wk  = __reduce_min_sync(0xFFFFFFFFu, fkey(bx));
        if (wk >= KEY_INF) break;                     // envelope complete
        unsigned bal = __ballot_sync(0xFFFFFFFFu, fkey(bx) == wk);
        int src = __ffs(bal) - 1;
        mc = __shfl_sync(0xFFFFFFFFu, bm, src);
        bc = __shfl_sync(0xFFFFFFFFu, bb, src);
    }

    // Pad the compact hull to HP lines with (0, -inf): neutral for max.
    for (int k = cnt + lane; k < HP; k += 32)
        hp[k] = make_float2(0.f, F_NINF);
    if (lane == 0) g_cnt[branch][d][w] = cnt;
}

// ───────────────────────── eval kernel ─────────────────────────
// 128 CTAs: bid = branch (bx>>6) x batch-group of 16 (bx&63). 512 threads.
// Warp = (quad = warp&3, wblk = warp>>2); lane handles w = wblk*64+wo*32+lane.
//
// SINGLE smem layout used by BOTH stager and reader:
//   line pair g (lines 2g,2g+1) of w lives at  buf + w*128 + ((g ^ (w&7))<<4)
// Bank check: addr/4 mod 32 = perm*4 + word, perm a permutation of 0..7 over
// 8 consecutive lanes -> every LDS.128 phase covers 32 distinct banks.
#define EVAL_SMEM (2 * 32768 + 256 + 64)

__global__ void __launch_bounds__(512, 1) eval_kernel(
    const float* __restrict__ val, float* __restrict__ out) {
    extern __shared__ char smem[];
    float* s_red = (float*)(smem + 65536);          // [16 warps][4]
    float* s_q   = (float*)(smem + 65536 + 256);    // [16]

    unsigned sbase;
    asm("{.reg .u64 t; cvta.to.shared.u64 t, %1; cvt.u32.u64 %0, t;}"
        : "=r"(sbase) : "l"(smem));

    const int t      = threadIdx.x;
    const int branch = blockIdx.x >> 6;
    const int grp    = blockIdx.x & 63;
    const int warp   = t >> 5;
    const int lane   = t & 31;
    const int quad   = warp & 3;
    const int wblk   = warp >> 2;

    float q[4];
#pragma unroll
    for (int i = 0; i < 4; i++) q[i] = val[grp * 16 + quad * 4 + i];

    // Stage layer 0 into buffer 0: 2048 float4 = 256 w * 8 granules.
    {
        const float4* src = &g_hullp[branch][0][0][0];
#pragma unroll
        for (int k = 0; k < 4; k++) {
            int n = t + (k << 9);                 // 0..2047
            int w = n >> 3, g = n & 7;
            unsigned dst = sbase + (unsigned)(w * 128 + ((g ^ (w & 7)) << 4));
            CP_ASYNC16(dst, src + n);
        }
        CP_COMMIT();
    }

    for (int d = 0; d < DEPTH; ++d) {
        if (d < DEPTH - 1) {                      // prefetch layer d+1
            const float4* src = &g_hullp[branch][d + 1][0][0];
            unsigned bufo = (unsigned)(((d + 1) & 1) << 15);
#pragma unroll
            for (int k = 0; k < 4; k++) {
                int n = t + (k << 9);
                int w = n >> 3, g = n & 7;
                unsigned dst = sbase + bufo + (unsigned)(w * 128 + ((g ^ (w & 7)) << 4));
                CP_ASYNC16(dst, src + n);
            }
            CP_COMMIT();
            CP_WAIT(1);                           // layer d resident, d+1 in flight
        } else {
            CP_WAIT(0);
        }
        __syncthreads();

        const char* hb = smem + ((d & 1) << 15);
        const int w0 = wblk * 64 + lane;

        int cw0 = __ldg(&g_cnt[branch][d][w0]);
        int cw1 = __ldg(&g_cnt[branch][d][w0 + 32]);

        float vmin[4] = {F_INF, F_INF, F_INF, F_INF};
#pragma unroll
        for (int wo = 0; wo < 2; wo++) {
            const int w = w0 + wo * 32;
            const int cw = wo ? cw1 : cw0;
            const char* hw = hb + w * 128;
            const int ws7 = w & 7;
            float vmax[4] = {F_NINF, F_NINF, F_NINF, F_NINF};
#pragma unroll
            for (int g = 0; g < 4; g++) {         // lines 0..7
                float4 p = *(const float4*)(hw + ((g ^ ws7) << 4));
#pragma unroll
                for (int i = 0; i < 4; i++)
                    vmax[i] = fmaxf(vmax[i],
                                    fmaxf(fmaf(q[i], p.x, p.y),
                                          fmaf(q[i], p.z, p.w)));
            }
            if (cw > 8) {                         // lines 8..15
#pragma unroll
                for (int g = 4; g < 8; g++) {
                    float4 p = *(const float4*)(hw + ((g ^ ws7) << 4));
#pragma unroll
                    for (int i = 0; i < 4; i++)
                        vmax[i] = fmaxf(vmax[i],
                                        fmaxf(fmaf(q[i], p.x, p.y),
                                              fmaf(q[i], p.z, p.w)));
                }
            }
            if (cw > HP) {                        // rare oversized hull: global tail
                const float2* fp = &g_hull[branch][d][w][0];
                for (int k = HP; k < cw; k++) {
                    float2 l2 = __ldg(fp + k);
#pragma unroll
                    for (int i = 0; i < 4; i++)
                        vmax[i] = fmaxf(vmax[i], fmaf(q[i], l2.x, l2.y));
                }
            }
#pragma unroll
            for (int i = 0; i < 4; i++) vmin[i] = fminf(vmin[i], vmax[i]);
        }

        // Warp-wide min over this warp's 64 w's (all lanes share the quad).
#pragma unroll
        for (int o = 1; o <= 16; o <<= 1)
#pragma unroll
            for (int i = 0; i < 4; i++)
                vmin[i] = fminf(vmin[i], __shfl_xor_sync(0xFFFFFFFFu, vmin[i], o));
        if (lane == 0)
#pragma unroll
            for (int i = 0; i < 4; i++) s_red[warp * 4 + i] = vmin[i];
        __syncthreads();   // also guarantees all reads of buffer d&1 are done
                           // before next iteration's prefetch overwrites it

        if (t < 16) {
            const int qq = t >> 2, ii = t & 3;
            float acc = s_red[qq * 4 + ii];
#pragma unroll
            for (int wb = 1; wb < 4; wb++)
                acc = fminf(acc, s_red[(wb * 4 + qq) * 4 + ii]);
            if (d == DEPTH - 1)
                out[branch * BATCH + grp * 16 + t] = acc;   // t == qq*4+ii
            else
                s_q[t] = acc;
        }
        if (d < DEPTH - 1) {
            __syncthreads();
#pragma unroll
            for (int i = 0; i < 4; i++) q[i] = s_q[quad * 4 + i];
        }
    }
}

extern "C" void kernel_launch(void* const* d_in, const int* in_sizes, int n_in,
                              void* d_out, int out_size) {
    const float* val = (const float*)d_in[0];
    const float* M1  = (const float*)d_in[1];
    const float* B1  = (const float*)d_in[2];
    const float* M2  = (const float*)d_in[3];
    const float* B2  = (const float*)d_in[4];
    float* out = (float*)d_out;

    cudaFuncSetAttribute(eval_kernel,
                         cudaFuncAttributeMaxDynamicSharedMemorySize, EVAL_SMEM);

    hull_kernel<<<(2 * DEPTH * WDIM * 32) / 256, 256>>>(M1, B1, M2, B2);
    eval_kernel<<<128, 512, EVAL_SMEM>>>(val, out);
}